// round 2
// baseline (speedup 1.0000x reference)
#include <cuda_runtime.h>
#include <math.h>

#define Bq 4
#define Sq 4096
#define Hq 1024
#define NHq 16
#define Dq 64
#define Rq 2
#define SCALEq 0.125f

// scratch (no allocation allowed)
__device__ float g_cnt[Bq*Rq*Sq];
__device__ float g_xsum[Bq*Rq*Hq];
__device__ float g_ksum[Bq*Rq*Hq];
__device__ float g_vsum[Bq*Rq*Hq];
__device__ float g_pdiff[Bq*NHq*Hq];
__device__ float g_bdiff[Bq*NHq];

// ---------------- init: zero xsum, seed ksum/vsum with S*bias ----------------
__global__ void k_init(const float* __restrict__ bk, const float* __restrict__ bv) {
    int i = blockIdx.x * blockDim.x + threadIdx.x;
    if (i < Bq*Rq*Hq) {
        int h = i & (Hq - 1);
        g_xsum[i] = 0.f;
        g_ksum[i] = 4096.f * bk[h];
        g_vsum[i] = 4096.f * bv[h];
    }
}

// ---------------- histogram of rand_idx per (b, r) ----------------
__global__ void k_hist(const int* __restrict__ idx) {
    __shared__ int sh[Sq];
    int b = blockIdx.x / Rq, r = blockIdx.x % Rq;
    for (int j = threadIdx.x; j < Sq; j += blockDim.x) sh[j] = 0;
    __syncthreads();
    for (int s = threadIdx.x; s < Sq; s += blockDim.x)
        atomicAdd(&sh[idx[(b*Sq + s)*Rq + r]], 1);
    __syncthreads();
    for (int j = threadIdx.x; j < Sq; j += blockDim.x)
        g_cnt[(b*Rq + r)*Sq + j] = (float)sh[j];
}

// ---------------- xsum[b,r,:] = sum_s cnt[b,r,s] * x[b,s,:] ----------------
#define SCHUNKS 32
__global__ void k_xsum(const float* __restrict__ x) {
    int b = blockIdx.z;
    int h = blockIdx.x * 256 + threadIdx.x;
    int s0 = blockIdx.y * (Sq / SCHUNKS);
    const float* cnt0 = &g_cnt[(b*Rq + 0)*Sq];
    const float* cnt1 = &g_cnt[(b*Rq + 1)*Sq];
    const float* xb = x + (size_t)b * Sq * Hq;
    float a0 = 0.f, a1 = 0.f;
    #pragma unroll 4
    for (int s = s0; s < s0 + Sq/SCHUNKS; s++) {
        float c0 = cnt0[s], c1 = cnt1[s];
        if (c0 == 0.f && c1 == 0.f) continue;   // ~13.5% of rows skipped
        float xv = xb[(size_t)s * Hq + h];
        a0 += c0 * xv;
        a1 += c1 * xv;
    }
    atomicAdd(&g_xsum[(b*Rq + 0)*Hq + h], a0);
    atomicAdd(&g_xsum[(b*Rq + 1)*Hq + h], a1);
}

// ---------------- ksum/vsum = xsum @ W  (+bias already seeded) ----------------
__global__ void k_proj(const float* __restrict__ Wk, const float* __restrict__ Wv) {
    // grid: (8 coltiles, 8 hchunks, 2), block 128
    int col = blockIdx.x * 128 + threadIdx.x;
    int hc  = blockIdx.y * 128;
    const float* W = blockIdx.z ? Wv : Wk;
    float* out     = blockIdx.z ? g_vsum : g_ksum;
    __shared__ float xs[8][128];
    for (int i = threadIdx.x; i < 8*128; i += 128) {
        int br = i >> 7, hl = i & 127;
        xs[br][hl] = g_xsum[br*Hq + hc + hl];
    }
    __syncthreads();
    float acc[8] = {0.f,0.f,0.f,0.f,0.f,0.f,0.f,0.f};
    for (int hl = 0; hl < 128; hl++) {
        float w = W[(size_t)(hc + hl) * Hq + col];
        #pragma unroll
        for (int br = 0; br < 8; br++) acc[br] += xs[br][hl] * w;
    }
    #pragma unroll
    for (int br = 0; br < 8; br++) atomicAdd(&out[br*Hq + col], acc[br]);
}

// ---------------- Pdiff[b,n,h] = scale * sum_d Wq[h,nD+d]*(ksum0-ksum1) ----------------
__global__ void k_pdiff(const float* __restrict__ Wq, const float* __restrict__ bq) {
    // grid 64: n = bx>>2, ht = bx&3 ; block 256
    int n  = blockIdx.x >> 2;
    int ht = blockIdx.x & 3;
    int h  = ht * 256 + threadIdx.x;
    __shared__ float kd[Bq][Dq];
    for (int i = threadIdx.x; i < Bq*Dq; i += 256) {
        int b = i >> 6, d = i & 63;
        kd[b][d] = g_ksum[(b*Rq + 0)*Hq + n*Dq + d] - g_ksum[(b*Rq + 1)*Hq + n*Dq + d];
    }
    __syncthreads();
    float acc[Bq] = {0.f,0.f,0.f,0.f};
    const float* wrow = Wq + (size_t)h * Hq + n * Dq;
    #pragma unroll 8
    for (int d = 0; d < Dq; d++) {
        float w = wrow[d];
        #pragma unroll
        for (int b = 0; b < Bq; b++) acc[b] += w * kd[b][d];
    }
    #pragma unroll
    for (int b = 0; b < Bq; b++)
        g_pdiff[(b*NHq + n)*Hq + h] = SCALEq * acc[b];

    if (ht == 0 && threadIdx.x < Bq) {
        int b = threadIdx.x;
        float s = 0.f;
        for (int d = 0; d < Dq; d++) s += bq[n*Dq + d] * kd[b][d];
        g_bdiff[b*NHq + n] = SCALEq * s;
    }
}

// ---------------- main fused pass: scores -> sigmoid -> blend v ----------------
#define SMEM_MAIN ((NHq*Hq + 2*Hq + 16) * sizeof(float))
__global__ void __launch_bounds__(256, 2)
k_main(const float* __restrict__ x, float* __restrict__ out) {
    extern __shared__ float sm[];
    float* sPd = sm;                 // [16][1024]
    float* sV0 = sm + NHq*Hq;        // [1024]
    float* sV1 = sV0 + Hq;           // [1024]
    float* sBd = sV1 + Hq;           // [16]

    int b = blockIdx.y;
    for (int i = threadIdx.x; i < NHq*Hq; i += 256) sPd[i] = g_pdiff[b*NHq*Hq + i];
    for (int i = threadIdx.x; i < Hq; i += 256) {
        sV0[i] = g_vsum[(b*Rq + 0)*Hq + i];
        sV1[i] = g_vsum[(b*Rq + 1)*Hq + i];
    }
    if (threadIdx.x < NHq) sBd[threadIdx.x] = g_bdiff[b*NHq + threadIdx.x];
    __syncthreads();

    int warp = threadIdx.x >> 5, lane = threadIdx.x & 31;
    int r0 = blockIdx.x * 32 + warp * 4;
    const float* xb = x + (size_t)b * Sq * Hq;
    float* ob = out + (size_t)b * Sq * Hq;

    const float* xr0 = xb + (size_t)(r0 + 0) * Hq;
    const float* xr1 = xb + (size_t)(r0 + 1) * Hq;
    const float* xr2 = xb + (size_t)(r0 + 2) * Hq;
    const float* xr3 = xb + (size_t)(r0 + 3) * Hq;

    float acc[4][NHq];
    #pragma unroll
    for (int i = 0; i < 4; i++)
        #pragma unroll
        for (int n = 0; n < NHq; n++) acc[i][n] = 0.f;

    float xv0 = xr0[lane], xv1 = xr1[lane], xv2 = xr2[lane], xv3 = xr3[lane];

    #pragma unroll 4
    for (int j = 0; j < 32; j++) {
        int h = lane + 32*j;
        float xn0, xn1, xn2, xn3;
        if (j < 31) {
            int h2 = h + 32;
            xn0 = xr0[h2]; xn1 = xr1[h2]; xn2 = xr2[h2]; xn3 = xr3[h2];
        }
        #pragma unroll
        for (int n = 0; n < NHq; n++) {
            float pd = sPd[n*Hq + h];
            acc[0][n] += xv0 * pd;
            acc[1][n] += xv1 * pd;
            acc[2][n] += xv2 * pd;
            acc[3][n] += xv3 * pd;
        }
        xv0 = xn0; xv1 = xn1; xv2 = xn2; xv3 = xn3;
    }

    // warp-reduce all 64 partials (butterfly -> every lane has full sums)
    #pragma unroll
    for (int i = 0; i < 4; i++)
        #pragma unroll
        for (int n = 0; n < NHq; n++) {
            float v = acc[i][n];
            v += __shfl_xor_sync(0xffffffffu, v, 16);
            v += __shfl_xor_sync(0xffffffffu, v, 8);
            v += __shfl_xor_sync(0xffffffffu, v, 4);
            v += __shfl_xor_sync(0xffffffffu, v, 2);
            v += __shfl_xor_sync(0xffffffffu, v, 1);
            acc[i][n] = 1.f / (1.f + __expf(-(v + sBd[n])));   // prob for y=0
        }

    const float4* v04 = (const float4*)sV0;
    const float4* v14 = (const float4*)sV1;
    #pragma unroll
    for (int i = 0; i < 4; i++) {
        float4* o4 = (float4*)(ob + (size_t)(r0 + i) * Hq);
        #pragma unroll
        for (int j = 0; j < 8; j++) {
            int h4 = lane + 32*j;                  // float4 index; head = h4>>4
            float ppA = acc[i][2*j];               // lane < 16 half
            float ppB = acc[i][2*j + 1];           // lane >= 16 half
            float pp = (lane & 16) ? ppB : ppA;
            float4 a = v04[h4];
            float4 c = v14[h4];
            float4 o;
            o.x = c.x + pp * (a.x - c.x);
            o.y = c.y + pp * (a.y - c.y);
            o.z = c.z + pp * (a.z - c.z);
            o.w = c.w + pp * (a.w - c.w);
            o4[h4] = o;
        }
    }
}

extern "C" void kernel_launch(void* const* d_in, const int* in_sizes, int n_in,
                              void* d_out, int out_size) {
    const float* x  = (const float*)d_in[0];
    // d_in[1] attention_mask: unused by reference
    const float* Wq = (const float*)d_in[2];
    const float* bq = (const float*)d_in[3];
    const float* Wk = (const float*)d_in[4];
    const float* bk = (const float*)d_in[5];
    const float* Wv = (const float*)d_in[6];
    const float* bv = (const float*)d_in[7];
    const int* idx  = (const int*)d_in[8];
    float* out = (float*)d_out;

    cudaFuncSetAttribute(k_main, cudaFuncAttributeMaxDynamicSharedMemorySize, (int)SMEM_MAIN);

    k_init<<<32, 256>>>(bk, bv);
    k_hist<<<Bq*Rq, 512>>>(idx);
    k_xsum<<<dim3(Hq/256, SCHUNKS, Bq), 256>>>(x);
    k_proj<<<dim3(8, 8, 2), 128>>>(Wk, Wv);
    k_pdiff<<<64, 256>>>(Wq, bq);
    k_main<<<dim3(Sq/32, Bq), 256, SMEM_MAIN>>>(x, out);
}

// round 3
// speedup vs baseline: 1.1971x; 1.1971x over previous
#include <cuda_runtime.h>
#include <math.h>

#define Bq 4
#define Sq 4096
#define Hq 1024
#define NHq 16
#define Dq 64
#define Rq 2
#define SCALEq 0.125f

// scratch (no allocation allowed)
__device__ float g_cnt[Bq*Rq*Sq];
__device__ float g_xsum[Bq*Rq*Hq];
__device__ float g_ksum[Bq*Rq*Hq];
__device__ float g_vsum[Bq*Rq*Hq];
__device__ float g_pdiff[Bq*NHq*Hq];
__device__ float g_bdiff[Bq*NHq];

// ---------------- hist + init fused: one block per (b, r) ----------------
__global__ void k_hist(const int* __restrict__ idx,
                       const float* __restrict__ bk, const float* __restrict__ bv) {
    __shared__ int sh[Sq];
    int br = blockIdx.x;                 // b*2 + r
    int b = br >> 1, r = br & 1;
    for (int j = threadIdx.x; j < Sq; j += blockDim.x) sh[j] = 0;
    // init xsum / seed ksum,vsum with S*bias (each block owns a unique br slice)
    for (int i = threadIdx.x; i < Hq; i += blockDim.x) {
        g_xsum[br*Hq + i] = 0.f;
        g_ksum[br*Hq + i] = 4096.f * bk[i];
        g_vsum[br*Hq + i] = 4096.f * bv[i];
    }
    __syncthreads();
    for (int s = threadIdx.x; s < Sq; s += blockDim.x)
        atomicAdd(&sh[idx[(b*Sq + s)*Rq + r]], 1);
    __syncthreads();
    for (int j = threadIdx.x; j < Sq; j += blockDim.x)
        g_cnt[br*Sq + j] = (float)sh[j];
}

// ---------------- xsum[b,r,:] = sum_s cnt[b,r,s] * x[b,s,:]  (float4, no branch) ----------------
#define SCHUNKS 64
#define SROWS (Sq / SCHUNKS)     // 64
__global__ void __launch_bounds__(256)
k_xsum(const float* __restrict__ x) {
    int b  = blockIdx.y;
    int h4 = threadIdx.x;                          // float4 index 0..255
    int s0 = blockIdx.x * SROWS;
    const float* cnt0 = &g_cnt[(b*Rq + 0)*Sq];
    const float* cnt1 = &g_cnt[(b*Rq + 1)*Sq];
    const float4* xb4 = (const float4*)(x + (size_t)b * Sq * Hq);
    float4 a0 = make_float4(0.f,0.f,0.f,0.f);
    float4 a1 = make_float4(0.f,0.f,0.f,0.f);
    #pragma unroll 4
    for (int s = s0; s < s0 + SROWS; s++) {
        float c0 = cnt0[s], c1 = cnt1[s];
        float4 xv = xb4[(size_t)s * 256 + h4];
        a0.x += c0*xv.x; a0.y += c0*xv.y; a0.z += c0*xv.z; a0.w += c0*xv.w;
        a1.x += c1*xv.x; a1.y += c1*xv.y; a1.z += c1*xv.z; a1.w += c1*xv.w;
    }
    float* o0 = &g_xsum[(b*Rq + 0)*Hq + h4*4];
    float* o1 = &g_xsum[(b*Rq + 1)*Hq + h4*4];
    atomicAdd(o0+0, a0.x); atomicAdd(o0+1, a0.y); atomicAdd(o0+2, a0.z); atomicAdd(o0+3, a0.w);
    atomicAdd(o1+0, a1.x); atomicAdd(o1+1, a1.y); atomicAdd(o1+2, a1.z); atomicAdd(o1+3, a1.w);
}

// ---------------- ksum/vsum += xsum @ W  (float4 weight loads) ----------------
#define HCHUNK 16
__global__ void __launch_bounds__(256)
k_proj(const float* __restrict__ Wk, const float* __restrict__ Wv) {
    // grid: (64 hchunks, 2), block 256; each thread owns 4 consecutive cols
    int c4 = threadIdx.x;                          // float4 col index 0..255
    int hc = blockIdx.x * HCHUNK;
    const float* W = blockIdx.y ? Wv : Wk;
    float* out     = blockIdx.y ? g_vsum : g_ksum;
    __shared__ float xs[8][HCHUNK];
    if (threadIdx.x < 8*HCHUNK) {
        int br = threadIdx.x / HCHUNK, hl = threadIdx.x % HCHUNK;
        xs[br][hl] = g_xsum[br*Hq + hc + hl];
    }
    __syncthreads();
    float4 acc[8];
    #pragma unroll
    for (int br = 0; br < 8; br++) acc[br] = make_float4(0.f,0.f,0.f,0.f);
    const float4* W4 = (const float4*)W;
    #pragma unroll
    for (int hl = 0; hl < HCHUNK; hl++) {
        float4 w = W4[(size_t)(hc + hl) * 256 + c4];
        #pragma unroll
        for (int br = 0; br < 8; br++) {
            float xv = xs[br][hl];
            acc[br].x += xv*w.x; acc[br].y += xv*w.y; acc[br].z += xv*w.z; acc[br].w += xv*w.w;
        }
    }
    #pragma unroll
    for (int br = 0; br < 8; br++) {
        float* o = &out[br*Hq + c4*4];
        atomicAdd(o+0, acc[br].x); atomicAdd(o+1, acc[br].y);
        atomicAdd(o+2, acc[br].z); atomicAdd(o+3, acc[br].w);
    }
}

// ---------------- Pdiff[b,n,h] = scale * sum_d Wq[h,nD+d]*(ksum0-ksum1) ----------------
__global__ void k_pdiff(const float* __restrict__ Wq, const float* __restrict__ bq) {
    // grid 64: n = bx>>2, ht = bx&3 ; block 256
    int n  = blockIdx.x >> 2;
    int ht = blockIdx.x & 3;
    int h  = ht * 256 + threadIdx.x;
    __shared__ float kd[Bq][Dq];
    for (int i = threadIdx.x; i < Bq*Dq; i += 256) {
        int b = i >> 6, d = i & 63;
        kd[b][d] = g_ksum[(b*Rq + 0)*Hq + n*Dq + d] - g_ksum[(b*Rq + 1)*Hq + n*Dq + d];
    }
    __syncthreads();
    float acc[Bq] = {0.f,0.f,0.f,0.f};
    const float* wrow = Wq + (size_t)h * Hq + n * Dq;
    #pragma unroll 8
    for (int d = 0; d < Dq; d++) {
        float w = wrow[d];
        #pragma unroll
        for (int b = 0; b < Bq; b++) acc[b] += w * kd[b][d];
    }
    #pragma unroll
    for (int b = 0; b < Bq; b++)
        g_pdiff[(b*NHq + n)*Hq + h] = SCALEq * acc[b];

    if (ht == 0 && threadIdx.x < Bq) {
        int b = threadIdx.x;
        float s = 0.f;
        for (int d = 0; d < Dq; d++) s += bq[n*Dq + d] * kd[b][d];
        g_bdiff[b*NHq + n] = SCALEq * s;
    }
}

// ---------------- main fused pass: scores -> sigmoid -> blend v ----------------
#define SMEM_MAIN ((NHq*Hq + 2*Hq + 16) * sizeof(float))
__global__ void __launch_bounds__(256, 2)
k_main(const float* __restrict__ x, float* __restrict__ out) {
    extern __shared__ float sm[];
    float* sPd = sm;                 // [16][1024]
    float* sV0 = sm + NHq*Hq;        // [1024]
    float* sV1 = sV0 + Hq;           // [1024]
    float* sBd = sV1 + Hq;           // [16]

    int b = blockIdx.y;
    {   // float4 staging of pdiff / vsum
        const float4* gp4 = (const float4*)&g_pdiff[b*NHq*Hq];
        float4* sp4 = (float4*)sPd;
        for (int i = threadIdx.x; i < NHq*Hq/4; i += 256) sp4[i] = gp4[i];
        const float4* v0g = (const float4*)&g_vsum[(b*Rq + 0)*Hq];
        const float4* v1g = (const float4*)&g_vsum[(b*Rq + 1)*Hq];
        float4* s04 = (float4*)sV0; float4* s14 = (float4*)sV1;
        for (int i = threadIdx.x; i < Hq/4; i += 256) { s04[i] = v0g[i]; s14[i] = v1g[i]; }
        if (threadIdx.x < NHq) sBd[threadIdx.x] = g_bdiff[b*NHq + threadIdx.x];
    }
    __syncthreads();

    int warp = threadIdx.x >> 5, lane = threadIdx.x & 31;
    int r0 = blockIdx.x * 32 + warp * 4;
    const float* xb = x + (size_t)b * Sq * Hq;
    float* ob = out + (size_t)b * Sq * Hq;

    const float4* xr4[4];
    #pragma unroll
    for (int i = 0; i < 4; i++)
        xr4[i] = (const float4*)(xb + (size_t)(r0 + i) * Hq);
    const float4* sPd4 = (const float4*)sPd;

    float acc[4][NHq];
    #pragma unroll
    for (int i = 0; i < 4; i++)
        #pragma unroll
        for (int n = 0; n < NHq; n++) acc[i][n] = 0.f;

    float4 xv[4];
    #pragma unroll
    for (int i = 0; i < 4; i++) xv[i] = xr4[i][lane];

    #pragma unroll
    for (int j = 0; j < 8; j++) {               // 8 * 32 lanes * float4 = 1024 h
        int h4 = lane + 32*j;
        float4 xn[4];
        if (j < 7) {
            #pragma unroll
            for (int i = 0; i < 4; i++) xn[i] = xr4[i][h4 + 32];
        }
        #pragma unroll
        for (int n = 0; n < NHq; n++) {
            float4 pd = sPd4[n*256 + h4];
            #pragma unroll
            for (int i = 0; i < 4; i++) {
                acc[i][n] += xv[i].x*pd.x + xv[i].y*pd.y + xv[i].z*pd.z + xv[i].w*pd.w;
            }
        }
        #pragma unroll
        for (int i = 0; i < 4; i++) xv[i] = xn[i];
    }

    // warp-reduce all 64 partials (butterfly -> every lane has full sums)
    #pragma unroll
    for (int i = 0; i < 4; i++)
        #pragma unroll
        for (int n = 0; n < NHq; n++) {
            float v = acc[i][n];
            v += __shfl_xor_sync(0xffffffffu, v, 16);
            v += __shfl_xor_sync(0xffffffffu, v, 8);
            v += __shfl_xor_sync(0xffffffffu, v, 4);
            v += __shfl_xor_sync(0xffffffffu, v, 2);
            v += __shfl_xor_sync(0xffffffffu, v, 1);
            acc[i][n] = 1.f / (1.f + __expf(-(v + sBd[n])));   // prob for y=0
        }

    const float4* v04 = (const float4*)sV0;
    const float4* v14 = (const float4*)sV1;
    #pragma unroll
    for (int i = 0; i < 4; i++) {
        float4* o4 = (float4*)(ob + (size_t)(r0 + i) * Hq);
        #pragma unroll
        for (int j = 0; j < 8; j++) {
            int h4 = lane + 32*j;                  // float4 index; head = h4>>4
            float ppA = acc[i][2*j];               // lane < 16 half
            float ppB = acc[i][2*j + 1];           // lane >= 16 half
            float pp = (lane & 16) ? ppB : ppA;
            float4 a = v04[h4];
            float4 c = v14[h4];
            float4 o;
            o.x = c.x + pp * (a.x - c.x);
            o.y = c.y + pp * (a.y - c.y);
            o.z = c.z + pp * (a.z - c.z);
            o.w = c.w + pp * (a.w - c.w);
            o4[h4] = o;
        }
    }
}

extern "C" void kernel_launch(void* const* d_in, const int* in_sizes, int n_in,
                              void* d_out, int out_size) {
    const float* x  = (const float*)d_in[0];
    // d_in[1] attention_mask: unused by reference
    const float* Wq = (const float*)d_in[2];
    const float* bq = (const float*)d_in[3];
    const float* Wk = (const float*)d_in[4];
    const float* bk = (const float*)d_in[5];
    const float* Wv = (const float*)d_in[6];
    const float* bv = (const float*)d_in[7];
    const int* idx  = (const int*)d_in[8];
    float* out = (float*)d_out;

    cudaFuncSetAttribute(k_main, cudaFuncAttributeMaxDynamicSharedMemorySize, (int)SMEM_MAIN);

    k_hist<<<Bq*Rq, 512>>>(idx, bk, bv);
    k_xsum<<<dim3(SCHUNKS, Bq), 256>>>(x);
    k_proj<<<dim3(Hq/HCHUNK, 2), 256>>>(Wk, Wv);
    k_pdiff<<<64, 256>>>(Wq, bq);
    k_main<<<dim3(Sq/32, Bq), 256, SMEM_MAIN>>>(x, out);
}

// round 4
// speedup vs baseline: 1.2295x; 1.0270x over previous
#include <cuda_runtime.h>
#include <math.h>

#define Bq 4
#define Sq 4096
#define Hq 1024
#define NHq 16
#define Dq 64
#define Rq 2
#define SCALEq 0.125f

typedef unsigned long long ull;

// scratch (no allocation allowed)
__device__ float g_cnt[Bq*Sq*Rq];        // layout [b][s][r] -> float2 loads
__device__ float g_xsum[Bq*Rq*Hq];
__device__ float g_ksum[Bq*Rq*Hq];
__device__ float g_vsum[Bq*Rq*Hq];
__device__ float g_pdiff[Bq*NHq*Hq];
__device__ float g_bdiff[Bq*NHq];

// ---------------- hist + init fused: one block per (b, r) ----------------
__global__ void k_hist(const int* __restrict__ idx,
                       const float* __restrict__ bk, const float* __restrict__ bv) {
    __shared__ int sh[Sq];
    int br = blockIdx.x;                 // b*2 + r
    int b = br >> 1, r = br & 1;
    for (int j = threadIdx.x; j < Sq; j += blockDim.x) sh[j] = 0;
    for (int i = threadIdx.x; i < Hq; i += blockDim.x) {
        g_xsum[br*Hq + i] = 0.f;
        g_ksum[br*Hq + i] = 4096.f * bk[i];
        g_vsum[br*Hq + i] = 4096.f * bv[i];
    }
    __syncthreads();
    for (int s = threadIdx.x; s < Sq; s += blockDim.x)
        atomicAdd(&sh[idx[(b*Sq + s)*Rq + r]], 1);
    __syncthreads();
    for (int j = threadIdx.x; j < Sq; j += blockDim.x)
        g_cnt[(b*Sq + j)*2 + r] = (float)sh[j];
}

// ---------------- xsum[b,r,:] = sum_s cnt[b,s,r] * x[b,s,:]  (float4, MLP8) ----------------
#define SCHUNKS 128
#define SROWS (Sq / SCHUNKS)     // 32
__global__ void __launch_bounds__(256)
k_xsum(const float* __restrict__ x) {
    int b  = blockIdx.y;
    int h4 = threadIdx.x;                          // float4 index 0..255
    int s0 = blockIdx.x * SROWS;
    const float2* cnt2 = (const float2*)&g_cnt[b*Sq*2];
    const float4* xb4 = (const float4*)(x + (size_t)b * Sq * Hq);
    float4 a0 = make_float4(0.f,0.f,0.f,0.f);
    float4 a1 = make_float4(0.f,0.f,0.f,0.f);
    #pragma unroll 8
    for (int s = s0; s < s0 + SROWS; s++) {
        float2 c = cnt2[s];
        float4 xv = xb4[(size_t)s * 256 + h4];
        a0.x += c.x*xv.x; a0.y += c.x*xv.y; a0.z += c.x*xv.z; a0.w += c.x*xv.w;
        a1.x += c.y*xv.x; a1.y += c.y*xv.y; a1.z += c.y*xv.z; a1.w += c.y*xv.w;
    }
    float* o0 = &g_xsum[(b*Rq + 0)*Hq + h4*4];
    float* o1 = &g_xsum[(b*Rq + 1)*Hq + h4*4];
    atomicAdd(o0+0, a0.x); atomicAdd(o0+1, a0.y); atomicAdd(o0+2, a0.z); atomicAdd(o0+3, a0.w);
    atomicAdd(o1+0, a1.x); atomicAdd(o1+1, a1.y); atomicAdd(o1+2, a1.z); atomicAdd(o1+3, a1.w);
}

// ---------------- ksum/vsum += xsum @ W  (float4 weight loads) ----------------
#define HCHUNK 16
__global__ void __launch_bounds__(256)
k_proj(const float* __restrict__ Wk, const float* __restrict__ Wv) {
    int c4 = threadIdx.x;                          // float4 col index 0..255
    int hc = blockIdx.x * HCHUNK;
    const float* W = blockIdx.y ? Wv : Wk;
    float* out     = blockIdx.y ? g_vsum : g_ksum;
    __shared__ float xs[8][HCHUNK];
    if (threadIdx.x < 8*HCHUNK) {
        int br = threadIdx.x / HCHUNK, hl = threadIdx.x % HCHUNK;
        xs[br][hl] = g_xsum[br*Hq + hc + hl];
    }
    __syncthreads();
    float4 acc[8];
    #pragma unroll
    for (int br = 0; br < 8; br++) acc[br] = make_float4(0.f,0.f,0.f,0.f);
    const float4* W4 = (const float4*)W;
    #pragma unroll
    for (int hl = 0; hl < HCHUNK; hl++) {
        float4 w = W4[(size_t)(hc + hl) * 256 + c4];
        #pragma unroll
        for (int br = 0; br < 8; br++) {
            float xv = xs[br][hl];
            acc[br].x += xv*w.x; acc[br].y += xv*w.y; acc[br].z += xv*w.z; acc[br].w += xv*w.w;
        }
    }
    #pragma unroll
    for (int br = 0; br < 8; br++) {
        float* o = &out[br*Hq + c4*4];
        atomicAdd(o+0, acc[br].x); atomicAdd(o+1, acc[br].y);
        atomicAdd(o+2, acc[br].z); atomicAdd(o+3, acc[br].w);
    }
}

// ---------------- Pdiff[b,n,h]: warp-per-row, fully coalesced Wq read ----------------
__global__ void __launch_bounds__(256)
k_pdiff(const float* __restrict__ Wq, const float* __restrict__ bq) {
    // grid 128, block 256 (8 warps); warp handles Wq row h = blockIdx.x*8 + warp
    __shared__ float kd[Bq][Hq];                   // ksum0 - ksum1, 16 KB
    int tid = threadIdx.x;
    for (int i = tid; i < Bq*Hq; i += 256) {
        int b = i >> 10, hc = i & (Hq-1);
        kd[b][hc] = g_ksum[(b*Rq + 0)*Hq + hc] - g_ksum[(b*Rq + 1)*Hq + hc];
    }
    __syncthreads();

    // bdiff (block 0 only, 64 threads)
    if (blockIdx.x == 0 && tid < Bq*NHq) {
        int b = tid >> 4, n = tid & 15;
        float s = 0.f;
        #pragma unroll 8
        for (int d = 0; d < Dq; d++) s += bq[n*Dq + d] * kd[b][n*Dq + d];
        g_bdiff[b*NHq + n] = SCALEq * s;
    }

    int warp = tid >> 5, lane = tid & 31;
    int h = blockIdx.x * 8 + warp;
    const float4* wr = (const float4*)(Wq + (size_t)h * Hq);

    float acc[Bq][8];
    #pragma unroll
    for (int b = 0; b < Bq; b++)
        #pragma unroll
        for (int j = 0; j < 8; j++) acc[b][j] = 0.f;

    #pragma unroll
    for (int j = 0; j < 8; j++) {
        int c4 = j*32 + lane;                      // float4 col index; head n = c4>>4
        float4 w = wr[c4];
        #pragma unroll
        for (int b = 0; b < Bq; b++) {
            float4 kv = ((const float4*)kd[b])[c4];
            acc[b][j] += w.x*kv.x + w.y*kv.y + w.z*kv.z + w.w*kv.w;
        }
    }
    // reduce within 16-lane groups (lanes 0-15 hold even heads' cols, 16-31 odd)
    #pragma unroll
    for (int b = 0; b < Bq; b++)
        #pragma unroll
        for (int j = 0; j < 8; j++) {
            float v = acc[b][j];
            v += __shfl_xor_sync(0xffffffffu, v, 8);
            v += __shfl_xor_sync(0xffffffffu, v, 4);
            v += __shfl_xor_sync(0xffffffffu, v, 2);
            v += __shfl_xor_sync(0xffffffffu, v, 1);
            acc[b][j] = v;
        }
    if ((lane & 15) == 0) {
        int half = lane >> 4;                      // 0: even heads, 1: odd heads
        #pragma unroll
        for (int b = 0; b < Bq; b++)
            #pragma unroll
            for (int j = 0; j < 8; j++) {
                int n = 2*j + half;
                g_pdiff[(b*NHq + n)*Hq + h] = SCALEq * acc[b][j];
            }
    }
}

// ---------------- main fused pass: scores (f32x2 packed) -> sigmoid -> blend v ----------------
#define SMEM_MAIN ((NHq*Hq + 2*Hq + 16) * sizeof(float))
__global__ void __launch_bounds__(128, 2)
k_main(const float* __restrict__ x, float* __restrict__ out) {
    extern __shared__ float sm[];
    float* sPd = sm;                 // [16][1024]
    float* sV0 = sm + NHq*Hq;        // [1024]
    float* sV1 = sV0 + Hq;           // [1024]
    float* sBd = sV1 + Hq;           // [16]

    int b = blockIdx.y;
    {   // float4 staging
        const float4* gp4 = (const float4*)&g_pdiff[b*NHq*Hq];
        float4* sp4 = (float4*)sPd;
        for (int i = threadIdx.x; i < NHq*Hq/4; i += 128) sp4[i] = gp4[i];
        const float4* v0g = (const float4*)&g_vsum[(b*Rq + 0)*Hq];
        const float4* v1g = (const float4*)&g_vsum[(b*Rq + 1)*Hq];
        float4* s04 = (float4*)sV0; float4* s14 = (float4*)sV1;
        for (int i = threadIdx.x; i < Hq/4; i += 128) { s04[i] = v0g[i]; s14[i] = v1g[i]; }
        if (threadIdx.x < NHq) sBd[threadIdx.x] = g_bdiff[b*NHq + threadIdx.x];
    }
    __syncthreads();

    int warp = threadIdx.x >> 5, lane = threadIdx.x & 31;
    int r0 = blockIdx.x * 16 + warp * 4;           // 4 warps * 4 rows = 16 rows/block
    const float* xb = x + (size_t)b * Sq * Hq;
    float* ob = out + (size_t)b * Sq * Hq;

    const double2* xr[4];
    #pragma unroll
    for (int i = 0; i < 4; i++)
        xr[i] = (const double2*)(xb + (size_t)(r0 + i) * Hq);
    const double2* sPdD = (const double2*)sPd;

    ull acc[4][NHq];
    #pragma unroll
    for (int i = 0; i < 4; i++)
        #pragma unroll
        for (int n = 0; n < NHq; n++) acc[i][n] = 0ull;

    // 2-deep prefetch of x tiles (double2 = 2 packed f32 pairs = same 16B as float4)
    double2 xa[4], xb2[4], xc[4];
    #pragma unroll
    for (int i = 0; i < 4; i++) { xa[i] = xr[i][lane]; xb2[i] = xr[i][lane + 32]; }

    #pragma unroll
    for (int j = 0; j < 8; j++) {                  // 8 * 32 lanes * 16B = 4KB row
        int h4 = lane + 32*j;
        if (j < 6) {
            #pragma unroll
            for (int i = 0; i < 4; i++) xc[i] = xr[i][h4 + 64];
        }
        ull xlo[4], xhi[4];
        #pragma unroll
        for (int i = 0; i < 4; i++) {
            xlo[i] = __double_as_longlong(xa[i].x);
            xhi[i] = __double_as_longlong(xa[i].y);
        }
        #pragma unroll
        for (int n = 0; n < NHq; n++) {
            double2 pdv = sPdD[n*256 + h4];
            ull plo = __double_as_longlong(pdv.x);
            ull phi = __double_as_longlong(pdv.y);
            #pragma unroll
            for (int i = 0; i < 4; i++) {
                asm("fma.rn.f32x2 %0, %1, %2, %0;" : "+l"(acc[i][n]) : "l"(xlo[i]), "l"(plo));
                asm("fma.rn.f32x2 %0, %1, %2, %0;" : "+l"(acc[i][n]) : "l"(xhi[i]), "l"(phi));
            }
        }
        #pragma unroll
        for (int i = 0; i < 4; i++) { xa[i] = xb2[i]; xb2[i] = xc[i]; }
    }

    // unpack packed halves, butterfly-reduce, sigmoid
    float prob[4][NHq];
    #pragma unroll
    for (int i = 0; i < 4; i++)
        #pragma unroll
        for (int n = 0; n < NHq; n++) {
            ull a = acc[i][n];
            float v = __uint_as_float((unsigned)(a & 0xffffffffu))
                    + __uint_as_float((unsigned)(a >> 32));
            v += __shfl_xor_sync(0xffffffffu, v, 16);
            v += __shfl_xor_sync(0xffffffffu, v, 8);
            v += __shfl_xor_sync(0xffffffffu, v, 4);
            v += __shfl_xor_sync(0xffffffffu, v, 2);
            v += __shfl_xor_sync(0xffffffffu, v, 1);
            prob[i][n] = 1.f / (1.f + __expf(-(v + sBd[n])));   // prob for y=0
        }

    const float4* v04 = (const float4*)sV0;
    const float4* v14 = (const float4*)sV1;
    #pragma unroll
    for (int i = 0; i < 4; i++) {
        float4* o4 = (float4*)(ob + (size_t)(r0 + i) * Hq);
        #pragma unroll
        for (int j = 0; j < 8; j++) {
            int h4 = lane + 32*j;                  // float4 index; head = h4>>4
            float ppA = prob[i][2*j];              // lane < 16 half
            float ppB = prob[i][2*j + 1];          // lane >= 16 half
            float pp = (lane & 16) ? ppB : ppA;
            float4 a = v04[h4];
            float4 c = v14[h4];
            float4 o;
            o.x = c.x + pp * (a.x - c.x);
            o.y = c.y + pp * (a.y - c.y);
            o.z = c.z + pp * (a.z - c.z);
            o.w = c.w + pp * (a.w - c.w);
            o4[h4] = o;
        }
    }
}

extern "C" void kernel_launch(void* const* d_in, const int* in_sizes, int n_in,
                              void* d_out, int out_size) {
    const float* x  = (const float*)d_in[0];
    // d_in[1] attention_mask: unused by reference
    const float* Wq = (const float*)d_in[2];
    const float* bq = (const float*)d_in[3];
    const float* Wk = (const float*)d_in[4];
    const float* bk = (const float*)d_in[5];
    const float* Wv = (const float*)d_in[6];
    const float* bv = (const float*)d_in[7];
    const int* idx  = (const int*)d_in[8];
    float* out = (float*)d_out;

    cudaFuncSetAttribute(k_main, cudaFuncAttributeMaxDynamicSharedMemorySize, (int)SMEM_MAIN);

    k_hist<<<Bq*Rq, 512>>>(idx, bk, bv);
    k_xsum<<<dim3(SCHUNKS, Bq), 256>>>(x);
    k_proj<<<dim3(Hq/HCHUNK, 2), 256>>>(Wk, Wv);
    k_pdiff<<<128, 256>>>(Wq, bq);
    k_main<<<dim3(Sq/16, Bq), 128, SMEM_MAIN>>>(x, out);
}